// round 15
// baseline (speedup 1.0000x reference)
#include <cuda_runtime.h>
#include <cstdint>
#include <math_constants.h>

// ---------------------------------------------------------------------------
// Problem constants
// ---------------------------------------------------------------------------
#define SQ   1024        // sequence length S
#define NB   8           // batch B
#define ID   256         // input dim I
#define HDIM 512         // hidden H
#define NL   4           // layers L
#define NHD  8           // num heads
#define HSZ  64          // head dim
#define FFD  1024        // ffn dim
#define EPSV 1e-5f
#define NEGV (-1e9f)

#define KT   16          // GEMM K tile
#define ASTR 20          // GEMM smem row stride (16+4): conflict-free LDSM
#define NSTG 3           // cp.async pipeline stages
#define BUFO (128 * ASTR * 4)   // bytes per stage per matrix

#define KSTR 68          // flash K/Q smem row stride (64+4): 17 odd -> LDSM ok
#define VSTR 68          // flash V^T smem row stride

// ---------------------------------------------------------------------------
// Scratch (static device globals — no runtime allocation allowed)
// ---------------------------------------------------------------------------
__device__ float g_xin[NB * SQ * ID];
__device__ float g_x[NB * SQ * HDIM];
__device__ float g_xt[NB * SQ * HDIM];       // tf32-rounded copy of x
__device__ float g_qkv[NB * SQ * 3 * HDIM];
__device__ float g_o[NB * SQ * HDIM];
__device__ float g_ffn[NB * SQ * FFD];
__device__ float g_tmp[NB * SQ * HDIM];
// pre-rounded weights: dense(131072) qkv(3145728) out(1048576) ffn1(2097152) ffn2(2097152)
__device__ float g_wt[8519680];

#define WT_DENSE 0
#define WT_QKV   131072
#define WT_OUT   (WT_QKV + 3145728)
#define WT_FFN1  (WT_OUT + 1048576)
#define WT_FFN2  (WT_FFN1 + 2097152)

// ---------------------------------------------------------------------------
// Helpers
// ---------------------------------------------------------------------------
__device__ __forceinline__ float to_tf32(float x) {
    uint32_t u;
    asm("cvt.rna.tf32.f32 %0, %1;" : "=r"(u) : "f"(x));
    return __uint_as_float(u);
}

__device__ __forceinline__ void mma_tf32(float* d, const uint32_t* a, const uint32_t* b) {
    asm volatile(
        "mma.sync.aligned.m16n8k8.row.col.f32.tf32.tf32.f32 "
        "{%0,%1,%2,%3}, {%4,%5,%6,%7}, {%8,%9}, {%0,%1,%2,%3};\n"
        : "+f"(d[0]), "+f"(d[1]), "+f"(d[2]), "+f"(d[3])
        : "r"(a[0]), "r"(a[1]), "r"(a[2]), "r"(a[3]), "r"(b[0]), "r"(b[1]));
}

__device__ __forceinline__ uint32_t smem_u32(const void* p) {
    return (uint32_t)__cvta_generic_to_shared(p);
}

__device__ __forceinline__ void ldsm4(uint32_t* r, uint32_t a) {
    asm volatile(
        "ldmatrix.sync.aligned.m8n8.x4.shared.b16 {%0,%1,%2,%3}, [%4];"
        : "=r"(r[0]), "=r"(r[1]), "=r"(r[2]), "=r"(r[3]) : "r"(a));
}

__device__ __forceinline__ void cp16(uint32_t dst, const float* src) {
    asm volatile("cp.async.cg.shared.global [%0], [%1], 16;"
                 :: "r"(dst), "l"(src) : "memory");
}

// ---------------------------------------------------------------------------
// Elementwise tf32 rounding (weights pre-pass). n % 4 == 0.
// ---------------------------------------------------------------------------
__global__ void round_tf32(const float* __restrict__ src, float* __restrict__ dst,
                           int n4) {
    int i = blockIdx.x * blockDim.x + threadIdx.x;
    if (i >= n4) return;
    float4 v = ((const float4*)src)[i];
    v.x = to_tf32(v.x); v.y = to_tf32(v.y);
    v.z = to_tf32(v.z); v.w = to_tf32(v.w);
    ((float4*)dst)[i] = v;
}

// ---------------------------------------------------------------------------
// (S, B, I) -> (B, S, I), tf32-rounded (feeds dense GEMM only)
// ---------------------------------------------------------------------------
__global__ void transpose_nodes(const float* __restrict__ nodes,
                                float* __restrict__ xin) {
    int idx = blockIdx.x * blockDim.x + threadIdx.x;
    if (idx >= NB * SQ * ID) return;
    int i  = idx % ID;
    int bs = idx / ID;
    int s  = bs % SQ;
    int b  = bs / SQ;
    xin[idx] = to_tf32(nodes[((size_t)s * NB + b) * ID + i]);
}

// ---------------------------------------------------------------------------
// TF32 TN GEMM, cp.async 3-stage pipeline. Inputs MUST be pre-rounded tf32.
// C[m,n] = act( sum_k A[m,k] * W[n,k] + bias[n] )
// mode: 0 = plain, 1 = relu + tf32-round, 2 = tf32-round.
// Block 128x128xKT, 8 warps (2M x 4N), warp tile 64x32, m16n8k8 MMA.
// ---------------------------------------------------------------------------
__global__ void __launch_bounds__(256)
gemm_tn_tf32(const float* __restrict__ A, int lda,
             const float* __restrict__ W, int ldb,
             const float* __restrict__ bias,
             float* __restrict__ C, int ldc,
             int K, int mode) {
    __shared__ float As[NSTG][128][ASTR];
    __shared__ float Bs[NSTG][128][ASTR];

    const int tid = threadIdx.x;
    const int bm = blockIdx.y * 128, bn = blockIdx.x * 128;
    const int r = tid >> 2, c4 = (tid & 3) * 4;
    const int wid = tid >> 5, lane = tid & 31;
    const int wm = (wid & 1) * 64, wn = (wid >> 1) * 32;
    const int qt = lane >> 3, rr = lane & 7;

    // ldmatrix addresses (stage 0, kk 0)
    uint32_t a_addr[4], b_addr[2];
#pragma unroll
    for (int mi = 0; mi < 4; mi++)
        a_addr[mi] = smem_u32(&As[0][wm + mi * 16 + (qt & 1) * 8 + rr][(qt >> 1) * 4]);
#pragma unroll
    for (int p = 0; p < 2; p++)
        b_addr[p] = smem_u32(&Bs[0][wn + p * 16 + (qt >> 1) * 8 + rr][(qt & 1) * 4]);

    const float* Ap0 = A + (size_t)(bm + r) * lda + c4;
    const float* Ap1 = Ap0 + (size_t)64 * lda;
    const float* Wp0 = W + (size_t)(bn + r) * ldb + c4;
    const float* Wp1 = Wp0 + (size_t)64 * ldb;

    const uint32_t sa0 = smem_u32(&As[0][r][c4]);
    const uint32_t sa1 = smem_u32(&As[0][r + 64][c4]);
    const uint32_t sb0 = smem_u32(&Bs[0][r][c4]);
    const uint32_t sb1 = smem_u32(&Bs[0][r + 64][c4]);

    const int nt = K / KT;

    auto load_stage = [&](int t) {
        if (t < nt) {
            const uint32_t off = (uint32_t)(t % NSTG) * BUFO;
            const int ko = t * KT;
            cp16(sa0 + off, Ap0 + ko);
            cp16(sa1 + off, Ap1 + ko);
            cp16(sb0 + off, Wp0 + ko);
            cp16(sb1 + off, Wp1 + ko);
        }
        asm volatile("cp.async.commit_group;" ::: "memory");
    };

    float acc[4][4][4];
#pragma unroll
    for (int mi = 0; mi < 4; mi++)
#pragma unroll
        for (int ni = 0; ni < 4; ni++)
#pragma unroll
            for (int c = 0; c < 4; c++) acc[mi][ni][c] = 0.f;

    load_stage(0);
    load_stage(1);

    for (int t = 0; t < nt; t++) {
        asm volatile("cp.async.wait_group %0;" :: "n"(1) : "memory");
        __syncthreads();                 // stage t visible to all; MMA(t-1) done by all
        load_stage(t + 2);               // overwrites stage (t-1)%3: safe after barrier
        const uint32_t off = (uint32_t)(t % NSTG) * BUFO;
#pragma unroll
        for (int kk = 0; kk < KT; kk += 8) {
            uint32_t af[4][4], bfr[2][4];
#pragma unroll
            for (int mi = 0; mi < 4; mi++)
                ldsm4(af[mi], a_addr[mi] + off + kk * 4);
#pragma unroll
            for (int p = 0; p < 2; p++)
                ldsm4(bfr[p], b_addr[p] + off + kk * 4);
#pragma unroll
            for (int mi = 0; mi < 4; mi++)
#pragma unroll
                for (int ni = 0; ni < 4; ni++)
                    mma_tf32(acc[mi][ni], af[mi], &bfr[ni >> 1][(ni & 1) * 2]);
        }
    }

    const int g = lane >> 2, tig = lane & 3;
#pragma unroll
    for (int mi = 0; mi < 4; mi++) {
        const int row0 = bm + wm + mi * 16 + g;
        const int row1 = row0 + 8;
#pragma unroll
        for (int ni = 0; ni < 4; ni++) {
            const int col = bn + wn + ni * 8 + 2 * tig;
            const float b0 = bias[col], b1 = bias[col + 1];
            float v0 = acc[mi][ni][0] + b0;
            float v1 = acc[mi][ni][1] + b1;
            float v2 = acc[mi][ni][2] + b0;
            float v3 = acc[mi][ni][3] + b1;
            if (mode == 1) {
                v0 = fmaxf(v0, 0.f); v1 = fmaxf(v1, 0.f);
                v2 = fmaxf(v2, 0.f); v3 = fmaxf(v3, 0.f);
            }
            if (mode != 0) {
                v0 = to_tf32(v0); v1 = to_tf32(v1);
                v2 = to_tf32(v2); v3 = to_tf32(v3);
            }
            *(float2*)(C + (size_t)row0 * ldc + col) = make_float2(v0, v1);
            *(float2*)(C + (size_t)row1 * ldc + col) = make_float2(v2, v3);
        }
    }
}

// ---------------------------------------------------------------------------
// Fused flash attention (mma.sync tf32 + ldmatrix). qkv is pre-rounded tf32,
// so staging does plain copies; Q scale 0.125 is an exact pow2.
// Per (b, h, 128-row q tile); 8 warps x 16 q rows; online softmax.
// Output written tf32-rounded (feeds out-proj GEMM only).
// ---------------------------------------------------------------------------
__global__ void __launch_bounds__(256)
flash_attn(const float* __restrict__ qkv, const int* __restrict__ dist,
           float* __restrict__ o) {
    __shared__ float sm[64 * KSTR + 64 * VSTR];   // Q overlays K/V in prologue
    float* Qs = sm;                               // [128][KSTR] (prologue only)
    float* Ks = sm;                               // [64][KSTR]  rows = kv
    float* Vt = sm + 64 * KSTR;                   // [64][VSTR]  rows = d (V^T)

    const int bz = blockIdx.y;
    const int b = bz >> 3, h = bz & 7;
    const int q0 = blockIdx.x * 128;
    const int tid = threadIdx.x;
    const int w = tid >> 5, lane = tid & 31;
    const int g = lane >> 2, tig = lane & 3;
    const int qt = lane >> 3, rr = lane & 7;
    const int rq = w * 16 + g;                    // local q row (first of pair)
    const bool row_head = (h < 6), shorth = (h < 4);

    // ---- stage Q tile (x 1/8 scale) and pull A-fragments ----
    {
        const int r = tid >> 2, c16 = (tid & 3) * 16;
        const float* src0 = qkv + ((size_t)(b * SQ + q0 + r) * (3 * HDIM)) + h * HSZ + c16;
#pragma unroll
        for (int it = 0; it < 2; it++) {
            const float* src = src0 + (size_t)it * 64 * (3 * HDIM);
            float* dst = Qs + (r + it * 64) * KSTR + c16;
#pragma unroll
            for (int i = 0; i < 4; i++) {
                float4 v = *(const float4*)(src + i * 4);
                dst[i * 4 + 0] = v.x * 0.125f;
                dst[i * 4 + 1] = v.y * 0.125f;
                dst[i * 4 + 2] = v.z * 0.125f;
                dst[i * 4 + 3] = v.w * 0.125f;
            }
        }
    }
    __syncthreads();

    uint32_t qf[8][4];
    {
        const uint32_t qa = smem_u32(Qs + (rq - g + (qt & 1) * 8 + rr) * KSTR + (qt >> 1) * 4);
#pragma unroll
        for (int kc = 0; kc < 8; kc++) ldsm4(qf[kc], qa + kc * 32);
    }
    __syncthreads();

    // ldmatrix addresses for K and V^T fragments (fixed for all tiles)
    uint32_t kf_addr[4], vf_addr[4];
#pragma unroll
    for (int p = 0; p < 4; p++) {
        kf_addr[p] = smem_u32(Ks + (p * 16 + (qt >> 1) * 8 + rr) * KSTR + (qt & 1) * 4);
        vf_addr[p] = smem_u32(Vt + (p * 16 + (qt >> 1) * 8 + rr) * VSTR + (qt & 1) * 4);
    }

    float acc_o[8][4];
#pragma unroll
    for (int j = 0; j < 8; j++)
#pragma unroll
        for (int c = 0; c < 4; c++) acc_o[j][c] = 0.f;

    float m0 = -CUDART_INF_F, m1 = -CUDART_INF_F, l0 = 0.f, l1 = 0.f;
    const int gr0 = q0 + rq, gr1 = gr0 + 8;       // global q rows
    const int* dr0 = dist + (size_t)b * SQ * SQ + (row_head ? (size_t)gr0 * SQ : 0);
    const int* dr1 = row_head ? dr0 + 8 * SQ : dr0;

    for (int t = 0; t < SQ / 64; t++) {
        const int kv0 = t * 64;
        // ---- stage K [kv][d] (plain copy; already tf32) ----
        {
            const int r = tid >> 2, c16 = (tid & 3) * 16;
            const float* ksrc = qkv + ((size_t)(b * SQ + kv0 + r) * (3 * HDIM)) +
                                HDIM + h * HSZ + c16;
            float* kd = Ks + r * KSTR + c16;
#pragma unroll
            for (int i = 0; i < 4; i++)
                *(float4*)(kd + i * 4) = *(const float4*)(ksrc + i * 4);
        }
        // ---- stage V transposed: Vt[d][kv] ----
        {
            const int rv = tid & 63, cv = (tid >> 6) * 16;
            const float* vsrc = qkv + ((size_t)(b * SQ + kv0 + rv) * (3 * HDIM)) +
                                2 * HDIM + h * HSZ + cv;
#pragma unroll
            for (int i = 0; i < 4; i++) {
                float4 v = *(const float4*)(vsrc + i * 4);
                Vt[(cv + i * 4 + 0) * VSTR + rv] = v.x;
                Vt[(cv + i * 4 + 1) * VSTR + rv] = v.y;
                Vt[(cv + i * 4 + 2) * VSTR + rv] = v.z;
                Vt[(cv + i * 4 + 3) * VSTR + rv] = v.w;
            }
        }
        __syncthreads();

        // ---- S = Q @ K^T (already scaled) ----
        float acc_s[8][4];
#pragma unroll
        for (int j = 0; j < 8; j++)
#pragma unroll
            for (int c = 0; c < 4; c++) acc_s[j][c] = 0.f;

#pragma unroll
        for (int kc = 0; kc < 8; kc++) {
            uint32_t kb[4][4];
#pragma unroll
            for (int p = 0; p < 4; p++) ldsm4(kb[p], kf_addr[p] + kc * 32);
#pragma unroll
            for (int j = 0; j < 8; j++)
                mma_tf32(acc_s[j], qf[kc], &kb[j >> 1][(j & 1) * 2]);
        }

        // ---- mask bias + tile max ----
        float tm0 = -CUDART_INF_F, tm1 = -CUDART_INF_F;
#pragma unroll
        for (int j = 0; j < 8; j++) {
            const int c0 = kv0 + j * 8 + 2 * tig, c1 = c0 + 1;
            const int d00 = dr0[c0], d01 = dr0[c1];
            const int d10 = dr1[c0], d11 = dr1[c1];
            const bool a00 = (gr0 == c0) || (shorth ? (d00 == 1) : (d00 >= 1));
            const bool a01 = (gr0 == c1) || (shorth ? (d01 == 1) : (d01 >= 1));
            const bool a10 = (gr1 == c0) || (shorth ? (d10 == 1) : (d10 >= 1));
            const bool a11 = (gr1 == c1) || (shorth ? (d11 == 1) : (d11 >= 1));
            acc_s[j][0] += a00 ? 0.f : NEGV;
            acc_s[j][1] += a01 ? 0.f : NEGV;
            acc_s[j][2] += a10 ? 0.f : NEGV;
            acc_s[j][3] += a11 ? 0.f : NEGV;
            tm0 = fmaxf(tm0, fmaxf(acc_s[j][0], acc_s[j][1]));
            tm1 = fmaxf(tm1, fmaxf(acc_s[j][2], acc_s[j][3]));
        }
        tm0 = fmaxf(tm0, __shfl_xor_sync(0xffffffffu, tm0, 1));
        tm0 = fmaxf(tm0, __shfl_xor_sync(0xffffffffu, tm0, 2));
        tm1 = fmaxf(tm1, __shfl_xor_sync(0xffffffffu, tm1, 1));
        tm1 = fmaxf(tm1, __shfl_xor_sync(0xffffffffu, tm1, 2));

        // ---- online softmax update ----
        const float mn0 = fmaxf(m0, tm0), mn1 = fmaxf(m1, tm1);
        const float al0 = __expf(m0 - mn0), al1 = __expf(m1 - mn1);
        float rs0 = 0.f, rs1 = 0.f;
#pragma unroll
        for (int j = 0; j < 8; j++) {
            acc_s[j][0] = __expf(acc_s[j][0] - mn0);
            acc_s[j][1] = __expf(acc_s[j][1] - mn0);
            acc_s[j][2] = __expf(acc_s[j][2] - mn1);
            acc_s[j][3] = __expf(acc_s[j][3] - mn1);
            rs0 += acc_s[j][0] + acc_s[j][1];
            rs1 += acc_s[j][2] + acc_s[j][3];
        }
        rs0 += __shfl_xor_sync(0xffffffffu, rs0, 1);
        rs0 += __shfl_xor_sync(0xffffffffu, rs0, 2);
        rs1 += __shfl_xor_sync(0xffffffffu, rs1, 1);
        rs1 += __shfl_xor_sync(0xffffffffu, rs1, 2);
        l0 = l0 * al0 + rs0;
        l1 = l1 * al1 + rs1;
        m0 = mn0; m1 = mn1;
#pragma unroll
        for (int j = 0; j < 8; j++) {
            acc_o[j][0] *= al0; acc_o[j][1] *= al0;
            acc_o[j][2] *= al1; acc_o[j][3] *= al1;
        }

        // ---- P: C-layout -> A-layout via quad shuffles ----
        const int sa = (lane & 28) | (tig >> 1);
        const int sb = sa + 2;
        const bool odd = tig & 1;
#pragma unroll
        for (int j = 0; j < 8; j++) {
            float v0a = __shfl_sync(0xffffffffu, acc_s[j][0], sa);
            float v1a = __shfl_sync(0xffffffffu, acc_s[j][1], sa);
            float v2a = __shfl_sync(0xffffffffu, acc_s[j][2], sa);
            float v3a = __shfl_sync(0xffffffffu, acc_s[j][3], sa);
            float v0b = __shfl_sync(0xffffffffu, acc_s[j][0], sb);
            float v1b = __shfl_sync(0xffffffffu, acc_s[j][1], sb);
            float v2b = __shfl_sync(0xffffffffu, acc_s[j][2], sb);
            float v3b = __shfl_sync(0xffffffffu, acc_s[j][3], sb);
            acc_s[j][0] = to_tf32(odd ? v1a : v0a);
            acc_s[j][1] = to_tf32(odd ? v3a : v2a);
            acc_s[j][2] = to_tf32(odd ? v1b : v0b);
            acc_s[j][3] = to_tf32(odd ? v3b : v2b);
        }

        // ---- O += P @ V (V^T fragments via ldmatrix) ----
#pragma unroll
        for (int kc = 0; kc < 8; kc++) {
            uint32_t pa[4];
            pa[0] = __float_as_uint(acc_s[kc][0]);
            pa[1] = __float_as_uint(acc_s[kc][1]);
            pa[2] = __float_as_uint(acc_s[kc][2]);
            pa[3] = __float_as_uint(acc_s[kc][3]);
            uint32_t vb[4][4];
#pragma unroll
            for (int p = 0; p < 4; p++) ldsm4(vb[p], vf_addr[p] + kc * 32);
#pragma unroll
            for (int jd = 0; jd < 8; jd++)
                mma_tf32(acc_o[jd], pa, &vb[jd >> 1][(jd & 1) * 2]);
        }
        __syncthreads();
    }

    // ---- epilogue: O /= l, tf32-rounded (feeds out-proj GEMM) ----
    const float inv0 = 1.f / l0, inv1 = 1.f / l1;
    float* ob = o + ((size_t)(b * SQ + gr0) * HDIM) + h * HSZ;
#pragma unroll
    for (int jd = 0; jd < 8; jd++) {
        const int c = jd * 8 + 2 * tig;
        *(float2*)(ob + c) = make_float2(to_tf32(acc_o[jd][0] * inv0),
                                         to_tf32(acc_o[jd][1] * inv0));
        *(float2*)(ob + (size_t)8 * HDIM + c) =
            make_float2(to_tf32(acc_o[jd][2] * inv1), to_tf32(acc_o[jd][3] * inv1));
    }
}

// ---------------------------------------------------------------------------
// LayerNorm over H=512, optional residual add, optional tf32 shadow copy.
// One block (256 thr) per row. out/res may alias.
// ---------------------------------------------------------------------------
__global__ void __launch_bounds__(256)
ln_kernel(const float* __restrict__ y, const float* __restrict__ res,
          const float* __restrict__ g, const float* __restrict__ bta,
          float* __restrict__ out, float* __restrict__ out_t) {
    __shared__ float red[256];
    const int t = threadIdx.x;
    const size_t base = (size_t)blockIdx.x * HDIM;

    float v0 = y[base + t];
    float v1 = y[base + t + 256];
    if (res) {
        v0 += res[base + t];
        v1 += res[base + t + 256];
    }

    red[t] = v0 + v1;
    __syncthreads();
    for (int off = 128; off > 0; off >>= 1) {
        if (t < off) red[t] += red[t + off];
        __syncthreads();
    }
    const float mean = red[0] * (1.f / HDIM);
    __syncthreads();

    const float d0 = v0 - mean, d1 = v1 - mean;
    red[t] = d0 * d0 + d1 * d1;
    __syncthreads();
    for (int off = 128; off > 0; off >>= 1) {
        if (t < off) red[t] += red[t + off];
        __syncthreads();
    }
    const float rs = rsqrtf(red[0] * (1.f / HDIM) + EPSV);

    const float o0 = d0 * rs * g[t] + bta[t];
    const float o1 = d1 * rs * g[t + 256] + bta[t + 256];
    out[base + t]       = o0;
    out[base + t + 256] = o1;
    if (out_t) {
        out_t[base + t]       = to_tf32(o0);
        out_t[base + t + 256] = to_tf32(o1);
    }
}

// ---------------------------------------------------------------------------
// Final batch-norm over B=8 samples of x[:,0,:]. out[b,h].
// ---------------------------------------------------------------------------
__global__ void bn_kernel(const float* __restrict__ x, const float* __restrict__ g,
                          const float* __restrict__ bb, float* __restrict__ out) {
    const int h = blockIdx.x * blockDim.x + threadIdx.x;
    if (h >= HDIM) return;
    float v[NB];
    float m = 0.f;
#pragma unroll
    for (int b = 0; b < NB; b++) {
        v[b] = x[(size_t)b * SQ * HDIM + h];
        m += v[b];
    }
    m *= (1.f / NB);
    float var = 0.f;
#pragma unroll
    for (int b = 0; b < NB; b++) {
        float d = v[b] - m;
        var += d * d;
    }
    var *= (1.f / NB);
    const float rs = rsqrtf(var + EPSV);
#pragma unroll
    for (int b = 0; b < NB; b++)
        out[b * HDIM + h] = (v[b] - m) * rs * g[h] + bb[h];
}

// ---------------------------------------------------------------------------
// Launch
// ---------------------------------------------------------------------------
extern "C" void kernel_launch(void* const* d_in, const int* in_sizes, int n_in,
                              void* d_out, int out_size) {
    (void)in_sizes; (void)n_in; (void)out_size;

    const float* nodes      = (const float*)d_in[0];
    const int*   dist       = (const int*)d_in[1];
    const float* dense_w    = (const float*)d_in[2];
    const float* dense_b    = (const float*)d_in[3];
    const float* dense_ln_g = (const float*)d_in[4];
    const float* dense_ln_b = (const float*)d_in[5];
    const float* qkv_w      = (const float*)d_in[6];
    const float* qkv_b      = (const float*)d_in[7];
    const float* out_w      = (const float*)d_in[8];
    const float* out_b      = (const float*)d_in[9];
    const float* ln1_g      = (const float*)d_in[10];
    const float* ln1_b      = (const float*)d_in[11];
    const float* ffn_w1     = (const float*)d_in[12];
    const float* ffn_b1     = (const float*)d_in[13];
    const float* ffn_w2     = (const float*)d_in[14];
    const float* ffn_b2     = (const float*)d_in[15];
    const float* ln2_g      = (const float*)d_in[16];
    const float* ln2_b      = (const float*)d_in[17];
    const float* bn_g       = (const float*)d_in[18];
    const float* bn_b       = (const float*)d_in[19];
    float* out = (float*)d_out;

    float *xin, *x, *xt, *qkv, *o, *ffn, *tmp, *wt;
    cudaGetSymbolAddress((void**)&xin, g_xin);
    cudaGetSymbolAddress((void**)&x,   g_x);
    cudaGetSymbolAddress((void**)&xt,  g_xt);
    cudaGetSymbolAddress((void**)&qkv, g_qkv);
    cudaGetSymbolAddress((void**)&o,   g_o);
    cudaGetSymbolAddress((void**)&ffn, g_ffn);
    cudaGetSymbolAddress((void**)&tmp, g_tmp);
    cudaGetSymbolAddress((void**)&wt,  g_wt);

    float* dense_wt = wt + WT_DENSE;
    float* qkv_wt   = wt + WT_QKV;
    float* out_wt   = wt + WT_OUT;
    float* ffn1_wt  = wt + WT_FFN1;
    float* ffn2_wt  = wt + WT_FFN2;

    // pre-round all weights to tf32 (once per launch; graph-capturable)
    round_tf32<<<(131072 / 4 + 255) / 256, 256>>>(dense_w, dense_wt, 131072 / 4);
    round_tf32<<<(3145728 / 4 + 255) / 256, 256>>>(qkv_w, qkv_wt, 3145728 / 4);
    round_tf32<<<(1048576 / 4 + 255) / 256, 256>>>(out_w, out_wt, 1048576 / 4);
    round_tf32<<<(2097152 / 4 + 255) / 256, 256>>>(ffn_w1, ffn1_wt, 2097152 / 4);
    round_tf32<<<(2097152 / 4 + 255) / 256, 256>>>(ffn_w2, ffn2_wt, 2097152 / 4);

    const int M = NB * SQ;  // 8192 rows

    // input transpose (tf32) + dense projection + LN (dual output)
    transpose_nodes<<<(NB * SQ * ID + 255) / 256, 256>>>(nodes, xin);
    gemm_tn_tf32<<<dim3(HDIM / 128, M / 128), 256>>>(xin, ID, dense_wt, ID, dense_b,
                                                     tmp, HDIM, ID, 0);
    ln_kernel<<<M, 256>>>(tmp, nullptr, dense_ln_g, dense_ln_b, x, xt);

    for (int l = 0; l < NL; l++) {
        // QKV projection (output tf32-rounded; feeds flash only)
        gemm_tn_tf32<<<dim3(3 * HDIM / 128, M / 128), 256>>>(
            xt, HDIM, qkv_wt + (size_t)l * 3 * HDIM * HDIM, HDIM,
            qkv_b + l * 3 * HDIM, qkv, 3 * HDIM, HDIM, 2);

        // fused attention (scores + mask + softmax + AV); output tf32-rounded
        flash_attn<<<dim3(SQ / 128, NB * NHD), 256>>>(qkv, dist, o);

        // output projection + residual LN (dual output)
        gemm_tn_tf32<<<dim3(HDIM / 128, M / 128), 256>>>(
            o, HDIM, out_wt + (size_t)l * HDIM * HDIM, HDIM,
            out_b + l * HDIM, tmp, HDIM, HDIM, 0);
        ln_kernel<<<M, 256>>>(tmp, x, ln1_g + l * HDIM, ln1_b + l * HDIM, x, xt);

        // FFN (ffn1 output relu + tf32-rounded; feeds ffn2 only)
        gemm_tn_tf32<<<dim3(FFD / 128, M / 128), 256>>>(
            xt, HDIM, ffn1_wt + (size_t)l * FFD * HDIM, HDIM,
            ffn_b1 + l * FFD, ffn, FFD, HDIM, 1);
        gemm_tn_tf32<<<dim3(HDIM / 128, M / 128), 256>>>(
            ffn, FFD, ffn2_wt + (size_t)l * HDIM * FFD, FFD,
            ffn_b2 + l * HDIM, tmp, HDIM, FFD, 0);
        ln_kernel<<<M, 256>>>(tmp, x, ln2_g + l * HDIM, ln2_b + l * HDIM, x, xt);
    }

    // final batch-norm over batch dim of x[:, 0, :]
    bn_kernel<<<1, HDIM>>>(x, bn_g, bn_b, out);
}

// round 17
// speedup vs baseline: 1.3319x; 1.3319x over previous
#include <cuda_runtime.h>
#include <cuda_fp16.h>
#include <cstdint>
#include <math_constants.h>

// ---------------------------------------------------------------------------
// Problem constants
// ---------------------------------------------------------------------------
#define SQ   1024        // sequence length S
#define NB   8           // batch B
#define ID   256         // input dim I
#define HDIM 512         // hidden H
#define NL   4           // layers L
#define NHD  8           // num heads
#define HSZ  64          // head dim
#define FFD  1024        // ffn dim
#define EPSV 1e-5f
#define NEGV (-1e9f)

#define KT   16          // GEMM K tile (halves) = one m16n8k16 step
#define ASTR 24          // GEMM smem row stride in halves (48B): r*3 mod 8 distinct
#define NSTG 3           // cp.async pipeline stages
#define BUFO (128 * ASTR * 2)   // bytes per stage per matrix (6144)

#define KSTR 72          // flash smem row stride in halves (144B = 9x16B, odd) -> LDSM ok

// ---------------------------------------------------------------------------
// Scratch (static device globals — no runtime allocation allowed)
// ---------------------------------------------------------------------------
__device__ __half g_xin[NB * SQ * ID];
__device__ float  g_x[NB * SQ * HDIM];
__device__ __half g_xt[NB * SQ * HDIM];       // fp16 copy of x (GEMM A input)
__device__ __half g_qkv[NB * SQ * 3 * HDIM];
__device__ __half g_o[NB * SQ * HDIM];
__device__ __half g_ffn[NB * SQ * FFD];
__device__ float  g_tmp[NB * SQ * HDIM];
// fp16 weights: dense(131072) qkv(3145728) out(1048576) ffn1(2097152) ffn2(2097152)
__device__ __half g_wt[8519680];

#define WT_DENSE 0
#define WT_QKV   131072
#define WT_OUT   (WT_QKV + 3145728)
#define WT_FFN1  (WT_OUT + 1048576)
#define WT_FFN2  (WT_FFN1 + 2097152)

// ---------------------------------------------------------------------------
// Helpers
// ---------------------------------------------------------------------------
__device__ __forceinline__ void mma_fp16(float* d, const uint32_t* a, const uint32_t* b) {
    asm volatile(
        "mma.sync.aligned.m16n8k16.row.col.f32.f16.f16.f32 "
        "{%0,%1,%2,%3}, {%4,%5,%6,%7}, {%8,%9}, {%0,%1,%2,%3};\n"
        : "+f"(d[0]), "+f"(d[1]), "+f"(d[2]), "+f"(d[3])
        : "r"(a[0]), "r"(a[1]), "r"(a[2]), "r"(a[3]), "r"(b[0]), "r"(b[1]));
}

__device__ __forceinline__ uint32_t smem_u32(const void* p) {
    return (uint32_t)__cvta_generic_to_shared(p);
}

__device__ __forceinline__ void ldsm4(uint32_t* r, uint32_t a) {
    asm volatile(
        "ldmatrix.sync.aligned.m8n8.x4.shared.b16 {%0,%1,%2,%3}, [%4];"
        : "=r"(r[0]), "=r"(r[1]), "=r"(r[2]), "=r"(r[3]) : "r"(a));
}

__device__ __forceinline__ void cp16(uint32_t dst, const void* src) {
    asm volatile("cp.async.cg.shared.global [%0], [%1], 16;"
                 :: "r"(dst), "l"(src) : "memory");
}

__device__ __forceinline__ uint32_t pack_h2(float lo, float hi) {
    __half2 h = __floats2half2_rn(lo, hi);
    return *(uint32_t*)&h;
}

// ---------------------------------------------------------------------------
// fp32 -> fp16 weight conversion pre-pass. n4 = n/4.
// ---------------------------------------------------------------------------
__global__ void to_half(const float* __restrict__ src, __half* __restrict__ dst,
                        int n4) {
    int i = blockIdx.x * blockDim.x + threadIdx.x;
    if (i >= n4) return;
    float4 v = ((const float4*)src)[i];
    __half2 h0 = __floats2half2_rn(v.x, v.y);
    __half2 h1 = __floats2half2_rn(v.z, v.w);
    ((__half2*)dst)[2 * i]     = h0;
    ((__half2*)dst)[2 * i + 1] = h1;
}

// ---------------------------------------------------------------------------
// (S, B, I) -> (B, S, I), fp16 (feeds dense GEMM only)
// ---------------------------------------------------------------------------
__global__ void transpose_nodes(const float* __restrict__ nodes,
                                __half* __restrict__ xin) {
    int idx = blockIdx.x * blockDim.x + threadIdx.x;
    if (idx >= NB * SQ * ID) return;
    int i  = idx % ID;
    int bs = idx / ID;
    int s  = bs % SQ;
    int b  = bs / SQ;
    xin[idx] = __float2half(nodes[((size_t)s * NB + b) * ID + i]);
}

// ---------------------------------------------------------------------------
// FP16 TN GEMM (fp32 accum), cp.async 3-stage pipeline.
// C[m,n] = act( sum_k A[m,k] * W[n,k] + bias[n] )
// mode: 0 = fp32 out, 1 = relu + fp16 out, 2 = fp16 out.
// Block 128x128x16, 8 warps (2M x 4N), warp tile 64x32, m16n8k16 MMA.
// ---------------------------------------------------------------------------
__global__ void __launch_bounds__(256)
gemm_tn_fp16(const __half* __restrict__ A, int lda,
             const __half* __restrict__ W, int ldb,
             const float* __restrict__ bias,
             void* __restrict__ C, int ldc,
             int K, int mode) {
    __shared__ __half As[NSTG][128][ASTR];
    __shared__ __half Bs[NSTG][128][ASTR];

    const int tid = threadIdx.x;
    const int bm = blockIdx.y * 128, bn = blockIdx.x * 128;
    const int r = tid >> 1, c8 = (tid & 1) * 8;
    const int wid = tid >> 5, lane = tid & 31;
    const int wm = (wid & 1) * 64, wn = (wid >> 1) * 32;
    const int qt = lane >> 3, rr = lane & 7;

    // ldmatrix addresses (stage 0)
    uint32_t a_addr[4], b_addr[2];
#pragma unroll
    for (int mi = 0; mi < 4; mi++)
        a_addr[mi] = smem_u32(&As[0][wm + mi * 16 + (qt & 1) * 8 + rr][(qt >> 1) * 8]);
#pragma unroll
    for (int p = 0; p < 2; p++)
        b_addr[p] = smem_u32(&Bs[0][wn + p * 16 + (qt >> 1) * 8 + rr][(qt & 1) * 8]);

    const __half* Ap = A + (size_t)(bm + r) * lda + c8;
    const __half* Wp = W + (size_t)(bn + r) * ldb + c8;
    const uint32_t sa = smem_u32(&As[0][r][c8]);
    const uint32_t sb = smem_u32(&Bs[0][r][c8]);

    const int nt = K / KT;

    auto load_stage = [&](int t) {
        if (t < nt) {
            const uint32_t off = (uint32_t)(t % NSTG) * BUFO;
            const int ko = t * KT;
            cp16(sa + off, Ap + ko);
            cp16(sb + off, Wp + ko);
        }
        asm volatile("cp.async.commit_group;" ::: "memory");
    };

    float acc[4][4][4];
#pragma unroll
    for (int mi = 0; mi < 4; mi++)
#pragma unroll
        for (int ni = 0; ni < 4; ni++)
#pragma unroll
            for (int c = 0; c < 4; c++) acc[mi][ni][c] = 0.f;

    load_stage(0);
    load_stage(1);

    for (int t = 0; t < nt; t++) {
        asm volatile("cp.async.wait_group %0;" :: "n"(1) : "memory");
        __syncthreads();                 // stage t visible; MMA(t-1) done by all
        load_stage(t + 2);               // overwrites stage (t-1)%3: safe
        const uint32_t off = (uint32_t)(t % NSTG) * BUFO;
        uint32_t af[4][4], bfr[2][4];
#pragma unroll
        for (int mi = 0; mi < 4; mi++)
            ldsm4(af[mi], a_addr[mi] + off);
#pragma unroll
        for (int p = 0; p < 2; p++)
            ldsm4(bfr[p], b_addr[p] + off);
#pragma unroll
        for (int mi = 0; mi < 4; mi++)
#pragma unroll
            for (int ni = 0; ni < 4; ni++)
                mma_fp16(acc[mi][ni], af[mi], &bfr[ni >> 1][(ni & 1) * 2]);
    }

    const int g = lane >> 2, tig = lane & 3;
#pragma unroll
    for (int mi = 0; mi < 4; mi++) {
        const int row0 = bm + wm + mi * 16 + g;
        const int row1 = row0 + 8;
#pragma unroll
        for (int ni = 0; ni < 4; ni++) {
            const int col = bn + wn + ni * 8 + 2 * tig;
            const float b0 = bias[col], b1 = bias[col + 1];
            float v0 = acc[mi][ni][0] + b0;
            float v1 = acc[mi][ni][1] + b1;
            float v2 = acc[mi][ni][2] + b0;
            float v3 = acc[mi][ni][3] + b1;
            if (mode == 1) {
                v0 = fmaxf(v0, 0.f); v1 = fmaxf(v1, 0.f);
                v2 = fmaxf(v2, 0.f); v3 = fmaxf(v3, 0.f);
            }
            if (mode == 0) {
                float* Cf = (float*)C;
                *(float2*)(Cf + (size_t)row0 * ldc + col) = make_float2(v0, v1);
                *(float2*)(Cf + (size_t)row1 * ldc + col) = make_float2(v2, v3);
            } else {
                __half* Ch = (__half*)C;
                *(__half2*)(Ch + (size_t)row0 * ldc + col) = __floats2half2_rn(v0, v1);
                *(__half2*)(Ch + (size_t)row1 * ldc + col) = __floats2half2_rn(v2, v3);
            }
        }
    }
}

// ---------------------------------------------------------------------------
// Fused flash attention, fp16 operands + fp32 accum.
// Per (b, h, 128-row q tile); 8 warps x 16 q rows; online softmax.
// K staged [kv][d], V staged transposed [d][kv]; P packed directly from
// C-layout accumulators into fp16 A-fragments (no shuffles needed).
// ---------------------------------------------------------------------------
__global__ void __launch_bounds__(256)
flash_attn(const __half* __restrict__ qkv, const int* __restrict__ dist,
           __half* __restrict__ o) {
    __shared__ __half sm[2 * 64 * KSTR];          // 18432 B; Q overlays K/V
    __half* Qs = sm;                              // [128][KSTR] (prologue only)
    __half* Ks = sm;                              // [64][KSTR]  rows = kv
    __half* Vt = sm + 64 * KSTR;                  // [64][KSTR]  rows = d (V^T)

    const int bz = blockIdx.y;
    const int b = bz >> 3, h = bz & 7;
    const int q0 = blockIdx.x * 128;
    const int tid = threadIdx.x;
    const int w = tid >> 5, lane = tid & 31;
    const int g = lane >> 2, tig = lane & 3;
    const int qt = lane >> 3, rr = lane & 7;
    const int rq = w * 16 + g;                    // local q row (first of pair)
    const bool row_head = (h < 6), shorth = (h < 4);

    // ---- stage Q tile (x 1/8 scale, exact) ----
    {
        const int r = tid >> 1, c32 = (tid & 1) * 32;
        const __half2 s = __float2half2_rn(0.125f);
        const __half* src = qkv + ((size_t)(b * SQ + q0 + r) * (3 * HDIM)) + h * HSZ + c32;
        __half* dst = Qs + r * KSTR + c32;
#pragma unroll
        for (int i = 0; i < 4; i++) {
            uint4 u = *(const uint4*)(src + i * 8);
            __half2* hp = (__half2*)&u;
            hp[0] = __hmul2(hp[0], s); hp[1] = __hmul2(hp[1], s);
            hp[2] = __hmul2(hp[2], s); hp[3] = __hmul2(hp[3], s);
            *(uint4*)(dst + i * 8) = u;
        }
    }
    __syncthreads();

    // Q fragments: 4 k16 chunks x 4 regs
    uint32_t qf[4][4];
    {
        const uint32_t qa = smem_u32(Qs + (w * 16 + (qt & 1) * 8 + rr) * KSTR + (qt >> 1) * 8);
#pragma unroll
        for (int kc = 0; kc < 4; kc++) ldsm4(qf[kc], qa + kc * 32);
    }
    __syncthreads();

    // ldmatrix addresses for K and V^T fragments (fixed for all tiles)
    uint32_t kf_addr[4], vf_addr[4];
#pragma unroll
    for (int p = 0; p < 4; p++) {
        kf_addr[p] = smem_u32(Ks + (p * 16 + (qt >> 1) * 8 + rr) * KSTR + (qt & 1) * 8);
        vf_addr[p] = smem_u32(Vt + (p * 16 + (qt >> 1) * 8 + rr) * KSTR + (qt & 1) * 8);
    }

    float acc_o[8][4];
#pragma unroll
    for (int j = 0; j < 8; j++)
#pragma unroll
        for (int c = 0; c < 4; c++) acc_o[j][c] = 0.f;

    float m0 = -CUDART_INF_F, m1 = -CUDART_INF_F, l0 = 0.f, l1 = 0.f;
    const int gr0 = q0 + rq, gr1 = gr0 + 8;       // global q rows
    const int* dr0 = dist + (size_t)b * SQ * SQ + (row_head ? (size_t)gr0 * SQ : 0);
    const int* dr1 = row_head ? dr0 + 8 * SQ : dr0;

    for (int t = 0; t < SQ / 64; t++) {
        const int kv0 = t * 64;
        // ---- stage K [kv][d] ----
        {
            const int r = tid >> 2, c16 = (tid & 3) * 16;
            const __half* ksrc = qkv + ((size_t)(b * SQ + kv0 + r) * (3 * HDIM)) +
                                 HDIM + h * HSZ + c16;
            __half* kd = Ks + r * KSTR + c16;
            *(uint4*)(kd)     = *(const uint4*)(ksrc);
            *(uint4*)(kd + 8) = *(const uint4*)(ksrc + 8);
        }
        // ---- stage V transposed: Vt[d][kv] ----
        {
            const int rv = tid & 63, cv = (tid >> 6) * 16;
            const __half* vsrc = qkv + ((size_t)(b * SQ + kv0 + rv) * (3 * HDIM)) +
                                 2 * HDIM + h * HSZ + cv;
            uint4 u0 = *(const uint4*)(vsrc);
            uint4 u1 = *(const uint4*)(vsrc + 8);
            const __half* hv0 = (const __half*)&u0;
            const __half* hv1 = (const __half*)&u1;
#pragma unroll
            for (int i = 0; i < 8; i++) {
                Vt[(cv + i) * KSTR + rv]     = hv0[i];
                Vt[(cv + 8 + i) * KSTR + rv] = hv1[i];
            }
        }
        __syncthreads();

        // ---- S = Q @ K^T (already scaled) ----
        float acc_s[8][4];
#pragma unroll
        for (int j = 0; j < 8; j++)
#pragma unroll
            for (int c = 0; c < 4; c++) acc_s[j][c] = 0.f;

#pragma unroll
        for (int kc = 0; kc < 4; kc++) {
            uint32_t kb[4][4];
#pragma unroll
            for (int p = 0; p < 4; p++) ldsm4(kb[p], kf_addr[p] + kc * 32);
#pragma unroll
            for (int j = 0; j < 8; j++)
                mma_fp16(acc_s[j], qf[kc], &kb[j >> 1][(j & 1) * 2]);
        }

        // ---- mask bias + tile max ----
        float tm0 = -CUDART_INF_F, tm1 = -CUDART_INF_F;
#pragma unroll
        for (int j = 0; j < 8; j++) {
            const int c0 = kv0 + j * 8 + 2 * tig, c1 = c0 + 1;
            const int d00 = dr0[c0], d01 = dr0[c1];
            const int d10 = dr1[c0], d11 = dr1[c1];
            const bool a00 = (gr0 == c0) || (shorth ? (d00 == 1) : (d00 >= 1));
            const bool a01 = (gr0 == c1) || (shorth ? (d01 == 1) : (d01 >= 1));
            const bool a10 = (gr1 == c0) || (shorth ? (d10 == 1) : (d10 >= 1));
            const bool a11 = (gr1 == c1) || (shorth ? (d11 == 1) : (d11 >= 1));
            acc_s[j][0] += a00 ? 0.f : NEGV;
            acc_s[j][1] += a01 ? 0.f : NEGV;
            acc_s[j][2] += a10 ? 0.f : NEGV;
            acc_s[j][3] += a11 ? 0.f : NEGV;
            tm0 = fmaxf(tm0, fmaxf(acc_s[j][0], acc_s[j][1]));
            tm1 = fmaxf(tm1, fmaxf(acc_s[j][2], acc_s[j][3]));
        }
        tm0 = fmaxf(tm0, __shfl_xor_sync(0xffffffffu, tm0, 1));
        tm0 = fmaxf(tm0, __shfl_xor_sync(0xffffffffu, tm0, 2));
        tm1 = fmaxf(tm1, __shfl_xor_sync(0xffffffffu, tm1, 1));
        tm1 = fmaxf(tm1, __shfl_xor_sync(0xffffffffu, tm1, 2));

        // ---- online softmax update ----
        const float mn0 = fmaxf(m0, tm0), mn1 = fmaxf(m1, tm1);
        const float al0 = __expf(m0 - mn0), al1 = __expf(m1 - mn1);
        float rs0 = 0.f, rs1 = 0.f;
#pragma unroll
        for (int j = 0; j < 8; j++) {
            acc_s[j][0] = __expf(acc_s[j][0] - mn0);
            acc_s[j][1] = __expf(acc_s[j][1] - mn0);
            acc_s[j][2] = __expf(acc_s[j][2] - mn1);
            acc_s[j][3] = __expf(acc_s[j][3] - mn1);
            rs0 += acc_s[j][0] + acc_s[j][1];
            rs1 += acc_s[j][2] + acc_s[j][3];
        }
        rs0 += __shfl_xor_sync(0xffffffffu, rs0, 1);
        rs0 += __shfl_xor_sync(0xffffffffu, rs0, 2);
        rs1 += __shfl_xor_sync(0xffffffffu, rs1, 1);
        rs1 += __shfl_xor_sync(0xffffffffu, rs1, 2);
        l0 = l0 * al0 + rs0;
        l1 = l1 * al1 + rs1;
        m0 = mn0; m1 = mn1;
#pragma unroll
        for (int j = 0; j < 8; j++) {
            acc_o[j][0] *= al0; acc_o[j][1] *= al0;
            acc_o[j][2] *= al1; acc_o[j][3] *= al1;
        }

        // ---- O += P @ V: pack P C-layout regs directly into fp16 A-frags ----
#pragma unroll
        for (int c = 0; c < 4; c++) {
            uint32_t pa[4];
            pa[0] = pack_h2(acc_s[2 * c][0],     acc_s[2 * c][1]);      // row g,   k0-7
            pa[1] = pack_h2(acc_s[2 * c][2],     acc_s[2 * c][3]);      // row g+8, k0-7
            pa[2] = pack_h2(acc_s[2 * c + 1][0], acc_s[2 * c + 1][1]);  // row g,   k8-15
            pa[3] = pack_h2(acc_s[2 * c + 1][2], acc_s[2 * c + 1][3]);  // row g+8, k8-15
            uint32_t vb[4][4];
#pragma unroll
            for (int p = 0; p < 4; p++) ldsm4(vb[p], vf_addr[p] + c * 32);
#pragma unroll
            for (int jd = 0; jd < 8; jd++)
                mma_fp16(acc_o[jd], pa, &vb[jd >> 1][(jd & 1) * 2]);
        }
        __syncthreads();
    }

    // ---- epilogue: O /= l, fp16 out (feeds out-proj GEMM) ----
    const float inv0 = 1.f / l0, inv1 = 1.f / l1;
    __half* ob = o + ((size_t)(b * SQ + gr0) * HDIM) + h * HSZ;
#pragma unroll
    for (int jd = 0; jd < 8; jd++) {
        const int c = jd * 8 + 2 * tig;
        *(__half2*)(ob + c) = __floats2half2_rn(acc_o[jd][0] * inv0, acc_o[jd][1] * inv0);
        *(__half2*)(ob + (size_t)8 * HDIM + c) =
            __floats2half2_rn(acc_o[jd][2] * inv1, acc_o[jd][3] * inv1);
    }
}

// ---------------------------------------------------------------------------
// LayerNorm over H=512, optional residual add, fp16 shadow copy.
// One block (256 thr) per row. out/res may alias.
// ---------------------------------------------------------------------------
__global__ void __launch_bounds__(256)
ln_kernel(const float* __restrict__ y, const float* __restrict__ res,
          const float* __restrict__ g, const float* __restrict__ bta,
          float* __restrict__ out, __half* __restrict__ out_t) {
    __shared__ float red[256];
    const int t = threadIdx.x;
    const size_t base = (size_t)blockIdx.x * HDIM;

    float v0 = y[base + t];
    float v1 = y[base + t + 256];
    if (res) {
        v0 += res[base + t];
        v1 += res[base + t + 256];
    }

    red[t] = v0 + v1;
    __syncthreads();
    for (int off = 128; off > 0; off >>= 1) {
        if (t < off) red[t] += red[t + off];
        __syncthreads();
    }
    const float mean = red[0] * (1.f / HDIM);
    __syncthreads();

    const float d0 = v0 - mean, d1 = v1 - mean;
    red[t] = d0 * d0 + d1 * d1;
    __syncthreads();
    for (int off = 128; off > 0; off >>= 1) {
        if (t < off) red[t] += red[t + off];
        __syncthreads();
    }
    const float rs = rsqrtf(red[0] * (1.f / HDIM) + EPSV);

    const float o0 = d0 * rs * g[t] + bta[t];
    const float o1 = d1 * rs * g[t + 256] + bta[t + 256];
    out[base + t]       = o0;
    out[base + t + 256] = o1;
    out_t[base + t]       = __float2half(o0);
    out_t[base + t + 256] = __float2half(o1);
}

// ---------------------------------------------------------------------------
// Final batch-norm over B=8 samples of x[:,0,:]. out[b,h].
// ---------------------------------------------------------------------------
__global__ void bn_kernel(const float* __restrict__ x, const float* __restrict__ g,
                          const float* __restrict__ bb, float* __restrict__ out) {
    const int h = blockIdx.x * blockDim.x + threadIdx.x;
    if (h >= HDIM) return;
    float v[NB];
    float m = 0.f;
#pragma unroll
    for (int b = 0; b < NB; b++) {
        v[b] = x[(size_t)b * SQ * HDIM + h];
        m += v[b];
    }
    m *= (1.f / NB);
    float var = 0.f;
#pragma unroll
    for (int b = 0; b < NB; b++) {
        float d = v[b] - m;
        var += d * d;
    }
    var *= (1.f / NB);
    const float rs = rsqrtf(var + EPSV);
#pragma unroll
    for (int b = 0; b < NB; b++)
        out[b * HDIM + h] = (v[b] - m) * rs * g[h] + bb[h];
}

// ---------------------------------------------------------------------------
// Launch
// ---------------------------------------------------------------------------
extern "C" void kernel_launch(void* const* d_in, const int* in_sizes, int n_in,
                              void* d_out, int out_size) {
    (void)in_sizes; (void)n_in; (void)out_size;

    const float* nodes      = (const float*)d_in[0];
    const int*   dist       = (const int*)d_in[1];
    const float* dense_w    = (const float*)d_in[2];
    const float* dense_b    = (const float*)d_in[3];
    const float* dense_ln_g = (const float*)d_in[4];
    const float* dense_ln_b = (const float*)d_in[5];
    const float* qkv_w      = (const float*)d_in[6];
    const float* qkv_b      = (const float*)d_in[7];
    const float* out_w      = (const float*)d_in[8];
    const float* out_b      = (const float*)d_in[9];
    const float* ln1_g      = (const float*)d_in[10];
    const float* ln1_b      = (const float*)d_in[11];
    const float* ffn_w1     = (const float*)d_in[12];
    const float* ffn_b1     = (const float*)d_in[13];
    const float* ffn_w2     = (const float*)d_in[14];
    const float* ffn_b2     = (const float*)d_in[15];
    const float* ln2_g      = (const float*)d_in[16];
    const float* ln2_b      = (const float*)d_in[17];
    const float* bn_g       = (const float*)d_in[18];
    const float* bn_b       = (const float*)d_in[19];
    float* out = (float*)d_out;

    __half *xin, *xt, *qkv, *o, *ffn, *wt;
    float *x, *tmp;
    cudaGetSymbolAddress((void**)&xin, g_xin);
    cudaGetSymbolAddress((void**)&x,   g_x);
    cudaGetSymbolAddress((void**)&xt,  g_xt);
    cudaGetSymbolAddress((void**)&qkv, g_qkv);
    cudaGetSymbolAddress((void**)&o,   g_o);
    cudaGetSymbolAddress((void**)&ffn, g_ffn);
    cudaGetSymbolAddress((void**)&tmp, g_tmp);
    cudaGetSymbolAddress((void**)&wt,  g_wt);

    __half* dense_wt = wt + WT_DENSE;
    __half* qkv_wt   = wt + WT_QKV;
    __half* out_wt   = wt + WT_OUT;
    __half* ffn1_wt  = wt + WT_FFN1;
    __half* ffn2_wt  = wt + WT_FFN2;

    // convert all weights to fp16 (once per launch; graph-capturable)
    to_half<<<(131072 / 4 + 255) / 256, 256>>>(dense_w, dense_wt, 131072 / 4);
    to_half<<<(3145728 / 4 + 255) / 256, 256>>>(qkv_w, qkv_wt, 3145728 / 4);
    to_half<<<(1048576 / 4 + 255) / 256, 256>>>(out_w, out_wt, 1048576 / 4);
    to_half<<<(2097152 / 4 + 255) / 256, 256>>>(ffn_w1, ffn1_wt, 2097152 / 4);
    to_half<<<(2097152 / 4 + 255) / 256, 256>>>(ffn_w2, ffn2_wt, 2097152 / 4);

    const int M = NB * SQ;  // 8192 rows

    // input transpose (fp16) + dense projection + LN (fp32 + fp16 shadow)
    transpose_nodes<<<(NB * SQ * ID + 255) / 256, 256>>>(nodes, xin);
    gemm_tn_fp16<<<dim3(HDIM / 128, M / 128), 256>>>(xin, ID, dense_wt, ID, dense_b,
                                                     tmp, HDIM, ID, 0);
    ln_kernel<<<M, 256>>>(tmp, nullptr, dense_ln_g, dense_ln_b, x, xt);

    for (int l = 0; l < NL; l++) {
        // QKV projection (fp16 out; feeds flash only)
        gemm_tn_fp16<<<dim3(3 * HDIM / 128, M / 128), 256>>>(
            xt, HDIM, qkv_wt + (size_t)l * 3 * HDIM * HDIM, HDIM,
            qkv_b + l * 3 * HDIM, qkv, 3 * HDIM, HDIM, 2);

        // fused attention (scores + mask + softmax + AV); fp16 out
        flash_attn<<<dim3(SQ / 128, NB * NHD), 256>>>(qkv, dist, o);

        // output projection (fp32 out) + residual LN
        gemm_tn_fp16<<<dim3(HDIM / 128, M / 128), 256>>>(
            o, HDIM, out_wt + (size_t)l * HDIM * HDIM, HDIM,
            out_b + l * HDIM, tmp, HDIM, HDIM, 0);
        ln_kernel<<<M, 256>>>(tmp, x, ln1_g + l * HDIM, ln1_b + l * HDIM, x, xt);

        // FFN (ffn1: relu + fp16 out; ffn2: fp32 out)
        gemm_tn_fp16<<<dim3(FFD / 128, M / 128), 256>>>(
            xt, HDIM, ffn1_wt + (size_t)l * FFD * HDIM, HDIM,
            ffn_b1 + l * FFD, ffn, FFD, HDIM, 1);
        gemm_tn_fp16<<<dim3(HDIM / 128, M / 128), 256>>>(
            ffn, FFD, ffn2_wt + (size_t)l * HDIM * FFD, FFD,
            ffn_b2 + l * HDIM, tmp, HDIM, FFD, 0);
        ln_kernel<<<M, 256>>>(tmp, x, ln2_g + l * HDIM, ln2_b + l * HDIM, x, xt);
    }

    // final batch-norm over batch dim of x[:, 0, :]
    bn_kernel<<<1, HDIM>>>(x, bn_g, bn_b, out);
}